// round 1
// baseline (speedup 1.0000x reference)
#include <cuda_runtime.h>

#define B_ 16
#define N_ 512
#define H_ 8
#define D_ 64
#define BM 64
#define BN 64
#define LDS_ 68
// 8 * log2(e): logits = (2qk - k2 + geo) * sqrt(D) , computed in base-2 domain
#define C2 11.541560327111707f

typedef unsigned long long u64;

__device__ __forceinline__ u64 pack2(float lo, float hi){
  u64 r; asm("mov.b64 %0, {%1, %2};" : "=l"(r) : "f"(lo), "f"(hi)); return r;
}
__device__ __forceinline__ void unpack2(u64 v, float& lo, float& hi){
  asm("mov.b64 {%0, %1}, %2;" : "=f"(lo), "=f"(hi) : "l"(v));
}
__device__ __forceinline__ u64 ffma2(u64 a, u64 b, u64 c){
  u64 d; asm("fma.rn.f32x2 %0, %1, %2, %3;" : "=l"(d) : "l"(a), "l"(b), "l"(c)); return d;
}
__device__ __forceinline__ u64 fmul2(u64 a, u64 b){
  u64 d; asm("mul.rn.f32x2 %0, %1, %2;" : "=l"(d) : "l"(a), "l"(b)); return d;
}

__global__ void __launch_bounds__(256) geo_attn(
    const float* __restrict__ q, const float* __restrict__ k,
    const float* __restrict__ v, const float* __restrict__ geo,
    float* __restrict__ out)
{
  extern __shared__ float sm[];
  float* qs  = sm;                 // [BM][LDS_]  q tile, row-major (n, d)
  float* kp  = qs + BM*LDS_;       // [D_][LDS_]  k^T tile (d, m); later reused as P[i][j]
  float* vs  = kp + BM*LDS_;       // [BN][LDS_]  v tile (m, d)
  float* k2s = vs + BM*LDS_;       // [BN]        ||k_m||^2

  const int qt  = blockIdx.x, h = blockIdx.y, b = blockIdx.z;
  const int tid = threadIdx.x;
  const int tx  = tid & 15, ty = tid >> 4;
  const int i0  = ty * 4;          // query rows owned
  const int j0  = tx * 4;          // key cols in S stage == d cols in O stage
  const int n0  = qt * BM;

  const float* qb = q   + ((size_t)((b*N_ + n0)*H_ + h))*D_;
  const float* kb = k   + ((size_t)(b*N_*H_ + h))*D_;
  const float* vb = v   + ((size_t)(b*N_*H_ + h))*D_;
  const float* gb = geo + (size_t)b*N_*N_ + (size_t)n0*N_;

  // ---- load q tile (coalesced, float4) ----
  {
    const int r = tid >> 2, c = tid & 3;
    const float* src = qb + (size_t)r*(H_*D_) + c*16;
    float* dst = qs + r*LDS_ + c*16;
    #pragma unroll
    for(int i=0;i<4;i++) *(float4*)(dst + 4*i) = *(const float4*)(src + 4*i);
  }

  float mrow[4], lrow[4];
  u64 o2[4][2];
  #pragma unroll
  for(int r=0;r<4;r++){ mrow[r] = -1e30f; lrow[r] = 0.f; o2[r][0]=0ull; o2[r][1]=0ull; }

  for(int mt=0; mt<N_/BN; mt++){
    const int m0 = mt*BN;
    __syncthreads();   // previous PV done reading kp(P)/vs before overwrite

    // ---- load k (transposed into kp) and v tiles ----
    {
      const int r = tid >> 2, c = tid & 3;
      const float* ksrc = kb + (size_t)(m0+r)*(H_*D_) + c*16;
      const float* vsrc = vb + (size_t)(m0+r)*(H_*D_) + c*16;
      #pragma unroll
      for(int i=0;i<4;i++){
        float4 kk = *(const float4*)(ksrc + 4*i);
        const int d = c*16 + 4*i;
        kp[(d+0)*LDS_ + r] = kk.x;
        kp[(d+1)*LDS_ + r] = kk.y;
        kp[(d+2)*LDS_ + r] = kk.z;
        kp[(d+3)*LDS_ + r] = kk.w;
        *(float4*)(vs + r*LDS_ + d) = *(const float4*)(vsrc + 4*i);
      }
    }
    __syncthreads();

    // ---- ||k||^2 per key row ----
    if(tid < BN){
      float ssum = 0.f;
      #pragma unroll
      for(int d=0; d<D_; d++){ float kv = kp[d*LDS_ + tid]; ssum = fmaf(kv, kv, ssum); }
      k2s[tid] = ssum;
    }
    __syncthreads();

    // ---- S = q . k (4x4 per thread, packed f32x2 FMAs) ----
    u64 acc2[4][2];
    #pragma unroll
    for(int r=0;r<4;r++){ acc2[r][0]=0ull; acc2[r][1]=0ull; }

    #pragma unroll
    for(int d=0; d<D_; d+=4){
      float4 aq[4];
      #pragma unroll
      for(int r=0;r<4;r++) aq[r] = *(const float4*)(qs + (i0+r)*LDS_ + d);
      #pragma unroll
      for(int dd=0; dd<4; dd++){
        u64 bb0 = *(const u64*)(kp + (d+dd)*LDS_ + j0);
        u64 bb1 = *(const u64*)(kp + (d+dd)*LDS_ + j0 + 2);
        #pragma unroll
        for(int r=0;r<4;r++){
          float a = (dd==0)?aq[r].x:(dd==1)?aq[r].y:(dd==2)?aq[r].z:aq[r].w;
          u64 ad = pack2(a, a);
          acc2[r][0] = ffma2(ad, bb0, acc2[r][0]);
          acc2[r][1] = ffma2(ad, bb1, acc2[r][1]);
        }
      }
    }

    // ---- logits + online softmax (base-2; q^2 dropped: constant per row) ----
    const float4 k2v = *(const float4*)(k2s + j0);
    float p[4][4];
    #pragma unroll
    for(int r=0;r<4;r++){
      const float4 g = *(const float4*)(gb + (size_t)(i0+r)*N_ + m0 + j0);
      float a0,a1,a2,a3;
      unpack2(acc2[r][0], a0, a1);
      unpack2(acc2[r][1], a2, a3);
      float s0 = C2*(2.f*a0 - k2v.x + g.x);
      float s1 = C2*(2.f*a1 - k2v.y + g.y);
      float s2 = C2*(2.f*a2 - k2v.z + g.z);
      float s3 = C2*(2.f*a3 - k2v.w + g.w);
      float mx = fmaxf(fmaxf(s0,s1), fmaxf(s2,s3));
      #pragma unroll
      for(int off=1; off<16; off<<=1)
        mx = fmaxf(mx, __shfl_xor_sync(0xffffffffu, mx, off));
      const float mnew = fmaxf(mrow[r], mx);
      const float al = exp2f(mrow[r] - mnew);
      mrow[r] = mnew;
      p[r][0] = exp2f(s0 - mnew);
      p[r][1] = exp2f(s1 - mnew);
      p[r][2] = exp2f(s2 - mnew);
      p[r][3] = exp2f(s3 - mnew);
      float rs = (p[r][0]+p[r][1]) + (p[r][2]+p[r][3]);
      #pragma unroll
      for(int off=1; off<16; off<<=1)
        rs += __shfl_xor_sync(0xffffffffu, rs, off);
      lrow[r] = lrow[r]*al + rs;
      u64 ad = pack2(al, al);
      o2[r][0] = fmul2(o2[r][0], ad);
      o2[r][1] = fmul2(o2[r][1], ad);
    }

    __syncthreads();   // all reads of kp (k^T) done
    #pragma unroll
    for(int r=0;r<4;r++){
      float4 pv; pv.x = p[r][0]; pv.y = p[r][1]; pv.z = p[r][2]; pv.w = p[r][3];
      *(float4*)(kp + (i0+r)*LDS_ + j0) = pv;   // P tile into kp buffer
    }
    __syncthreads();

    // ---- O += P @ V  (thread owns rows i0..i0+3, d-cols j0..j0+3) ----
    #pragma unroll
    for(int j=0; j<BN; j+=4){
      float4 ap[4];
      #pragma unroll
      for(int r=0;r<4;r++) ap[r] = *(const float4*)(kp + (i0+r)*LDS_ + j);
      #pragma unroll
      for(int jj=0; jj<4; jj++){
        u64 vv0 = *(const u64*)(vs + (j+jj)*LDS_ + j0);
        u64 vv1 = *(const u64*)(vs + (j+jj)*LDS_ + j0 + 2);
        #pragma unroll
        for(int r=0;r<4;r++){
          float pf = (jj==0)?ap[r].x:(jj==1)?ap[r].y:(jj==2)?ap[r].z:ap[r].w;
          u64 pd = pack2(pf, pf);
          o2[r][0] = ffma2(pd, vv0, o2[r][0]);
          o2[r][1] = ffma2(pd, vv1, o2[r][1]);
        }
      }
    }
  }

  // ---- epilogue: normalize and store ----
  float* ob = out + ((size_t)((b*N_ + n0)*H_ + h))*D_;
  #pragma unroll
  for(int r=0;r<4;r++){
    const float inv = 1.f / lrow[r];
    float a0,a1,a2,a3;
    unpack2(o2[r][0], a0, a1);
    unpack2(o2[r][1], a2, a3);
    float4 res; res.x = a0*inv; res.y = a1*inv; res.z = a2*inv; res.w = a3*inv;
    *(float4*)(ob + (size_t)(i0+r)*(H_*D_) + j0) = res;
  }
}

extern "C" void kernel_launch(void* const* d_in, const int* in_sizes, int n_in,
                              void* d_out, int out_size) {
  const float* q = (const float*)d_in[0];
  const float* k = (const float*)d_in[1];
  const float* v = (const float*)d_in[2];
  const float* g = (const float*)d_in[3];
  float* out = (float*)d_out;

  const int smem_bytes = (3*BM*LDS_ + BN) * (int)sizeof(float);  // 52480
  cudaFuncSetAttribute(geo_attn, cudaFuncAttributeMaxDynamicSharedMemorySize, smem_bytes);

  dim3 grid(N_/BM, H_, B_);
  geo_attn<<<grid, 256, smem_bytes>>>(q, k, v, g, out);
}

// round 3
// speedup vs baseline: 1.6676x; 1.6676x over previous
#include <cuda_runtime.h>
#include <cuda_bf16.h>

#define B_ 16
#define N_ 512
#define H_ 8
#define D_ 64
#define BM 128
#define BN 64
#define NTILES 8
// 8 * log2(e): logits computed in base-2 domain, scale sqrt(D)=8 folded in
#define C2 11.541560327111707f

// smem byte offsets
#define KHI 0
#define KLO 8192
#define VTHI 16384
#define VTLO 24576
#define K2P 32768
#define K2S 33792
#define SMEM_BYTES 34048

typedef unsigned int u32;

__device__ __forceinline__ u32 swz(u32 x){ return x ^ ((x >> 3) & 0x70u); }

__device__ __forceinline__ float ex2(float x){
  float r; asm("ex2.approx.f32 %0, %1;" : "=f"(r) : "f"(x)); return r;
}

// split (a,b) fp32 pair -> packed bf16 hi pair (return) + packed bf16 lo pair
__device__ __forceinline__ u32 packsplit(float a, float b, u32& lo){
  __nv_bfloat16 ha = __float2bfloat16(a), hb = __float2bfloat16(b);
  float ra = a - __bfloat162float(ha), rb = b - __bfloat162float(hb);
  __nv_bfloat16 la = __float2bfloat16(ra), lb = __float2bfloat16(rb);
  lo = (u32)__bfloat16_as_ushort(la) | ((u32)__bfloat16_as_ushort(lb) << 16);
  return (u32)__bfloat16_as_ushort(ha) | ((u32)__bfloat16_as_ushort(hb) << 16);
}

__device__ __forceinline__ void mma16816(float* c, u32 a0, u32 a1, u32 a2, u32 a3,
                                         u32 b0, u32 b1){
  asm volatile(
    "mma.sync.aligned.m16n8k16.row.col.f32.bf16.bf16.f32 "
    "{%0,%1,%2,%3}, {%4,%5,%6,%7}, {%8,%9}, {%0,%1,%2,%3};"
    : "+f"(c[0]), "+f"(c[1]), "+f"(c[2]), "+f"(c[3])
    : "r"(a0), "r"(a1), "r"(a2), "r"(a3), "r"(b0), "r"(b1));
}

__global__ void __launch_bounds__(256, 2) geo_attn_mma(
    const float* __restrict__ q, const float* __restrict__ k,
    const float* __restrict__ v, const float* __restrict__ geo,
    float* __restrict__ out)
{
  extern __shared__ __align__(128) char smc[];
  const int tid = threadIdx.x, w = tid >> 5, l = tid & 31;
  const int qr = l >> 2;                  // fragment row within 8
  const int qc = l & 3;                   // fragment col group
  const int r0 = w * 16 + qr;             // local q row (first of the pair)
  const int qt = blockIdx.x, h = blockIdx.y, b = blockIdx.z;
  const int n0 = qt * BM;
  const int rowstride = H_ * D_;          // floats between consecutive n

  // ---- Q A-fragments straight from global (rows r0, r0+8), hi/lo split ----
  u32 aqh[4][4], aql[4][4];
  {
    const float* qb = q + ((size_t)(b*N_ + n0 + r0)*H_ + h)*D_;
    #pragma unroll
    for (int ks = 0; ks < 4; ks++){
      const int c0 = ks*16 + qc*2;
      float2 x00 = *(const float2*)(qb + c0);
      float2 x10 = *(const float2*)(qb + 8*rowstride + c0);
      float2 x01 = *(const float2*)(qb + c0 + 8);
      float2 x11 = *(const float2*)(qb + 8*rowstride + c0 + 8);
      aqh[ks][0] = packsplit(x00.x, x00.y, aql[ks][0]);
      aqh[ks][1] = packsplit(x10.x, x10.y, aql[ks][1]);
      aqh[ks][2] = packsplit(x01.x, x01.y, aql[ks][2]);
      aqh[ks][3] = packsplit(x11.x, x11.y, aql[ks][3]);
    }
  }

  float oacc[NTILES][4];
  #pragma unroll
  for (int t = 0; t < NTILES; t++){
    oacc[t][0]=0.f; oacc[t][1]=0.f; oacc[t][2]=0.f; oacc[t][3]=0.f;
  }
  float mold0 = -1e30f, mold1 = -1e30f, ls0 = 0.f, ls1 = 0.f;

  const float* grow = geo + (size_t)b*(N_*N_) + (size_t)(n0 + r0)*N_ + qc*2;

  for (int mt = 0; mt < NTILES; mt++){
    const int m0 = mt * BN;
    __syncthreads();   // all reads of K/Vt smem from previous tile done

    // ---- load K (K-major hi/lo) + V transposed (hi/lo) + k2 partials ----
    {
      const int r = tid >> 2, c4 = tid & 3, d0 = c4 * 16;
      const float* ksrc = k + ((size_t)(b*N_ + m0 + r)*H_ + h)*D_ + d0;
      const float* vsrc = v + ((size_t)(b*N_ + m0 + r)*H_ + h)*D_ + d0;
      float k2p = 0.f;
      u32 hp[8], lp[8];
      #pragma unroll
      for (int c = 0; c < 4; c++){
        float4 x = *(const float4*)(ksrc + c*4);
        k2p += x.x*x.x + x.y*x.y + x.z*x.z + x.w*x.w;
        hp[c*2]   = packsplit(x.x, x.y, lp[c*2]);
        hp[c*2+1] = packsplit(x.z, x.w, lp[c*2+1]);
      }
      const u32 o0 = swz((u32)(r*128 + d0*2));
      const u32 o1 = swz((u32)(r*128 + d0*2 + 16));
      *(uint4*)(smc + KHI + o0) = make_uint4(hp[0], hp[1], hp[2], hp[3]);
      *(uint4*)(smc + KHI + o1) = make_uint4(hp[4], hp[5], hp[6], hp[7]);
      *(uint4*)(smc + KLO + o0) = make_uint4(lp[0], lp[1], lp[2], lp[3]);
      *(uint4*)(smc + KLO + o1) = make_uint4(lp[4], lp[5], lp[6], lp[7]);
      ((float*)(smc + K2P))[r*4 + c4] = k2p;
      #pragma unroll
      for (int c = 0; c < 4; c++){
        float4 x = *(const float4*)(vsrc + c*4);
        float xs[4] = {x.x, x.y, x.z, x.w};
        #pragma unroll
        for (int i = 0; i < 4; i++){
          const int d = d0 + c*4 + i;
          __nv_bfloat16 hv = __float2bfloat16(xs[i]);
          float rv = xs[i] - __bfloat162float(hv);
          __nv_bfloat16 lv = __float2bfloat16(rv);
          const u32 toff = swz((u32)(d*128 + r*2));
          *(__nv_bfloat16*)(smc + VTHI + toff) = hv;
          *(__nv_bfloat16*)(smc + VTLO + toff) = lv;
        }
      }
    }
    __syncthreads();

    // finalize k2 while everyone starts S mmas (no hazard: barrier below)
    if (tid < BN){
      const float* kp = (const float*)(smc + K2P) + tid*4;
      ((float*)(smc + K2S))[tid] = (kp[0] + kp[1]) + (kp[2] + kp[3]);
    }

    // ---- S = Q @ K^T, 3-term bf16 split ----
    float sacc[NTILES][4];
    #pragma unroll
    for (int t = 0; t < NTILES; t++){
      sacc[t][0]=0.f; sacc[t][1]=0.f; sacc[t][2]=0.f; sacc[t][3]=0.f;
    }
    #pragma unroll
    for (int nt = 0; nt < NTILES; nt++){
      const u32 rowb = (u32)((nt*8 + qr)*128 + qc*4);
      #pragma unroll
      for (int ks = 0; ks < 4; ks++){
        const u32 off0 = swz(rowb + ks*32);
        const u32 off1 = swz(rowb + ks*32 + 16);
        u32 bh0 = *(const u32*)(smc + KHI + off0);
        u32 bh1 = *(const u32*)(smc + KHI + off1);
        u32 bl0 = *(const u32*)(smc + KLO + off0);
        u32 bl1 = *(const u32*)(smc + KLO + off1);
        mma16816(sacc[nt], aqh[ks][0], aqh[ks][1], aqh[ks][2], aqh[ks][3], bh0, bh1);
        mma16816(sacc[nt], aqh[ks][0], aqh[ks][1], aqh[ks][2], aqh[ks][3], bl0, bl1);
        mma16816(sacc[nt], aql[ks][0], aql[ks][1], aql[ks][2], aql[ks][3], bh0, bh1);
      }
    }
    __syncthreads();   // k2s visible to all

    // ---- logits + online softmax (per-warp rows, shuffle over 4 lanes) ----
    float mx0 = -1e30f, mx1 = -1e30f;
    #pragma unroll
    for (int nt = 0; nt < NTILES; nt++){
      const float2 kk = *(const float2*)((const float*)(smc + K2S) + nt*8 + qc*2);
      const float2 g0 = *(const float2*)(grow + m0 + nt*8);
      const float2 g1 = *(const float2*)(grow + 8*N_ + m0 + nt*8);
      float t00 = C2*(2.f*sacc[nt][0] - kk.x + g0.x);
      float t01 = C2*(2.f*sacc[nt][1] - kk.y + g0.y);
      float t10 = C2*(2.f*sacc[nt][2] - kk.x + g1.x);
      float t11 = C2*(2.f*sacc[nt][3] - kk.y + g1.y);
      sacc[nt][0]=t00; sacc[nt][1]=t01; sacc[nt][2]=t10; sacc[nt][3]=t11;
      mx0 = fmaxf(mx0, fmaxf(t00, t01));
      mx1 = fmaxf(mx1, fmaxf(t10, t11));
    }
    #pragma unroll
    for (int d = 1; d < 4; d <<= 1){
      mx0 = fmaxf(mx0, __shfl_xor_sync(0xffffffffu, mx0, d));
      mx1 = fmaxf(mx1, __shfl_xor_sync(0xffffffffu, mx1, d));
    }
    const float mnew0 = fmaxf(mold0, mx0), mnew1 = fmaxf(mold1, mx1);
    const float al0 = ex2(mold0 - mnew0), al1 = ex2(mold1 - mnew1);
    mold0 = mnew0; mold1 = mnew1;
    float ps0 = 0.f, ps1 = 0.f;
    #pragma unroll
    for (int nt = 0; nt < NTILES; nt++){
      float p0 = ex2(sacc[nt][0] - mnew0);
      float p1 = ex2(sacc[nt][1] - mnew0);
      float p2 = ex2(sacc[nt][2] - mnew1);
      float p3 = ex2(sacc[nt][3] - mnew1);
      sacc[nt][0]=p0; sacc[nt][1]=p1; sacc[nt][2]=p2; sacc[nt][3]=p3;
      ps0 += p0 + p1; ps1 += p2 + p3;
    }
    #pragma unroll
    for (int d = 1; d < 4; d <<= 1){
      ps0 += __shfl_xor_sync(0xffffffffu, ps0, d);
      ps1 += __shfl_xor_sync(0xffffffffu, ps1, d);
    }
    ls0 = ls0*al0 + ps0;
    ls1 = ls1*al1 + ps1;
    #pragma unroll
    for (int t = 0; t < NTILES; t++){
      oacc[t][0]*=al0; oacc[t][1]*=al0; oacc[t][2]*=al1; oacc[t][3]*=al1;
    }

    // ---- O += P @ V  (P repacked in registers as A-fragments) ----
    #pragma unroll
    for (int ks = 0; ks < 4; ks++){
      u32 pl0, pl1, pl2, pl3;
      u32 ph0 = packsplit(sacc[2*ks][0],   sacc[2*ks][1],   pl0);
      u32 ph1 = packsplit(sacc[2*ks][2],   sacc[2*ks][3],   pl1);
      u32 ph2 = packsplit(sacc[2*ks+1][0], sacc[2*ks+1][1], pl2);
      u32 ph3 = packsplit(sacc[2*ks+1][2], sacc[2*ks+1][3], pl3);
      #pragma unroll
      for (int dt = 0; dt < NTILES; dt++){
        const u32 rowb = (u32)((dt*8 + qr)*128 + qc*4);
        const u32 off0 = swz(rowb + ks*32);
        const u32 off1 = swz(rowb + ks*32 + 16);
        u32 vh0 = *(const u32*)(smc + VTHI + off0);
        u32 vh1 = *(const u32*)(smc + VTHI + off1);
        u32 vl0 = *(const u32*)(smc + VTLO + off0);
        u32 vl1 = *(const u32*)(smc + VTLO + off1);
        mma16816(oacc[dt], ph0, ph1, ph2, ph3, vh0, vh1);
        mma16816(oacc[dt], ph0, ph1, ph2, ph3, vl0, vl1);
        mma16816(oacc[dt], pl0, pl1, pl2, pl3, vh0, vh1);
      }
    }
  }

  // ---- epilogue ----
  {
    const float inv0 = 1.f / ls0, inv1 = 1.f / ls1;
    float* ob = out + ((size_t)(b*N_ + n0 + r0)*H_ + h)*D_ + qc*2;
    #pragma unroll
    for (int dt = 0; dt < NTILES; dt++){
      float2 r4a; r4a.x = oacc[dt][0]*inv0; r4a.y = oacc[dt][1]*inv0;
      float2 r4b; r4b.x = oacc[dt][2]*inv1; r4b.y = oacc[dt][3]*inv1;
      *(float2*)(ob + dt*8) = r4a;
      *(float2*)(ob + 8*rowstride + dt*8) = r4b;
    }
  }
}

extern "C" void kernel_launch(void* const* d_in, const int* in_sizes, int n_in,
                              void* d_out, int out_size) {
  const float* q = (const float*)d_in[0];
  const float* k = (const float*)d_in[1];
  const float* v = (const float*)d_in[2];
  const float* g = (const float*)d_in[3];
  float* out = (float*)d_out;

  cudaFuncSetAttribute(geo_attn_mma, cudaFuncAttributeMaxDynamicSharedMemorySize, SMEM_BYTES);
  dim3 grid(N_/BM, H_, B_);
  geo_attn_mma<<<grid, 256, SMEM_BYTES>>>(q, k, v, g, out);
}

// round 4
// speedup vs baseline: 2.3646x; 1.4179x over previous
#include <cuda_runtime.h>
#include <cuda_fp16.h>

#define B_ 16
#define N_ 512
#define H_ 8
#define D_ 64
#define BM 128
#define BN 64
#define NTILES 8
// 8 * log2(e): logits computed in base-2 domain, scale sqrt(D)=8 folded in
#define C2 11.541560327111707f

// smem byte offsets (fp16 tiles: 64 rows x 128B, SW128 swizzled)
#define KHI 0
#define KLO 8192
#define VHI 16384
#define VLO 24576
#define K2P 32768
#define K2S 33792
#define SMEM_BYTES 34048

typedef unsigned int u32;

__device__ __forceinline__ u32 swz(u32 x){ return x ^ ((x >> 3) & 0x70u); }

__device__ __forceinline__ u32 s2u(const void* p){
  u32 a; asm("{ .reg .u64 t; cvta.to.shared.u64 t, %1; cvt.u32.u64 %0, t; }" : "=r"(a) : "l"(p));
  return a;
}
__device__ __forceinline__ float ex2(float x){
  float r; asm("ex2.approx.f32 %0, %1;" : "=f"(r) : "f"(x)); return r;
}
// split (a,b) fp32 pair -> packed fp16 hi pair (return) + packed fp16 lo (residual) pair
__device__ __forceinline__ u32 packsplit(float a, float b, u32& lo){
  __half ha = __float2half_rn(a), hb = __float2half_rn(b);
  __half la = __float2half_rn(a - __half2float(ha));
  __half lb = __float2half_rn(b - __half2float(hb));
  lo = (u32)__half_as_ushort(la) | ((u32)__half_as_ushort(lb) << 16);
  return (u32)__half_as_ushort(ha) | ((u32)__half_as_ushort(hb) << 16);
}
__device__ __forceinline__ u32 packh(float a, float b){
  __half ha = __float2half_rn(a), hb = __float2half_rn(b);
  return (u32)__half_as_ushort(ha) | ((u32)__half_as_ushort(hb) << 16);
}
__device__ __forceinline__ void mma16816(float* c, u32 a0, u32 a1, u32 a2, u32 a3,
                                         u32 b0, u32 b1){
  asm volatile(
    "mma.sync.aligned.m16n8k16.row.col.f32.f16.f16.f32 "
    "{%0,%1,%2,%3}, {%4,%5,%6,%7}, {%8,%9}, {%0,%1,%2,%3};"
    : "+f"(c[0]), "+f"(c[1]), "+f"(c[2]), "+f"(c[3])
    : "r"(a0), "r"(a1), "r"(a2), "r"(a3), "r"(b0), "r"(b1));
}
__device__ __forceinline__ void ldm4(u32 addr, u32& r0, u32& r1, u32& r2, u32& r3){
  asm volatile("ldmatrix.sync.aligned.m8n8.x4.shared.b16 {%0,%1,%2,%3}, [%4];"
    : "=r"(r0), "=r"(r1), "=r"(r2), "=r"(r3) : "r"(addr));
}
__device__ __forceinline__ void ldm4t(u32 addr, u32& r0, u32& r1, u32& r2, u32& r3){
  asm volatile("ldmatrix.sync.aligned.m8n8.x4.trans.shared.b16 {%0,%1,%2,%3}, [%4];"
    : "=r"(r0), "=r"(r1), "=r"(r2), "=r"(r3) : "r"(addr));
}

__global__ void __launch_bounds__(256, 2) geo_attn_mma(
    const float* __restrict__ q, const float* __restrict__ k,
    const float* __restrict__ v, const float* __restrict__ geo,
    float* __restrict__ out)
{
  extern __shared__ __align__(128) char smc[];
  const u32 smb = s2u(smc);
  const int tid = threadIdx.x, w = tid >> 5, l = tid & 31;
  const int qr = l >> 2;                  // fragment row within 8
  const int qc = l & 3;                   // fragment col group
  const int r0 = w * 16 + qr;             // local q row (first of the pair)
  const int qt = blockIdx.x, h = blockIdx.y, b = blockIdx.z;
  const int n0 = qt * BM;
  const int rowstride = H_ * D_;          // floats between consecutive n

  // per-lane ldmatrix row-address fragments (matrix id = l>>3, row = l&7)
  const u32 kfrag = (u32)((l & 7) * 128 + (l >> 3) * 16);
  const u32 vfrag = (u32)(((l >> 3) & 1) * 1024 + (l & 7) * 128 + (l >> 4) * 16);

  // ---- Q A-fragments straight from global (rows r0, r0+8), fp16 hi/lo split ----
  u32 aqh[4][4], aql[4][4];
  {
    const float* qb = q + ((size_t)(b*N_ + n0 + r0)*H_ + h)*D_;
    #pragma unroll
    for (int ks = 0; ks < 4; ks++){
      const int c0 = ks*16 + qc*2;
      float2 x00 = *(const float2*)(qb + c0);
      float2 x10 = *(const float2*)(qb + 8*rowstride + c0);
      float2 x01 = *(const float2*)(qb + c0 + 8);
      float2 x11 = *(const float2*)(qb + 8*rowstride + c0 + 8);
      aqh[ks][0] = packsplit(x00.x, x00.y, aql[ks][0]);
      aqh[ks][1] = packsplit(x10.x, x10.y, aql[ks][1]);
      aqh[ks][2] = packsplit(x01.x, x01.y, aql[ks][2]);
      aqh[ks][3] = packsplit(x11.x, x11.y, aql[ks][3]);
    }
  }

  float oacc[NTILES][4];
  #pragma unroll
  for (int t = 0; t < NTILES; t++){
    oacc[t][0]=0.f; oacc[t][1]=0.f; oacc[t][2]=0.f; oacc[t][3]=0.f;
  }
  float mold0 = -1e30f, mold1 = -1e30f, ls0 = 0.f, ls1 = 0.f;

  const float* grow = geo + (size_t)b*(N_*N_) + (size_t)(n0 + r0)*N_ + qc*2;

  for (int mt = 0; mt < NTILES; mt++){
    const int m0 = mt * BN;
    __syncthreads();   // all reads of K/V smem from previous tile done

    // ---- load K and V (both row-major [key][d], fp16 hi/lo) + k2 partials ----
    {
      const int r = tid >> 2, c4 = tid & 3, d0 = c4 * 16;
      const float* ksrc = k + ((size_t)(b*N_ + m0 + r)*H_ + h)*D_ + d0;
      const float* vsrc = v + ((size_t)(b*N_ + m0 + r)*H_ + h)*D_ + d0;
      const u32 o0 = swz((u32)(r*128 + d0*2));
      const u32 o1 = swz((u32)(r*128 + d0*2 + 16));
      float k2p = 0.f;
      {
        u32 hp[8], lp[8];
        #pragma unroll
        for (int c = 0; c < 4; c++){
          float4 x = *(const float4*)(ksrc + c*4);
          k2p += x.x*x.x + x.y*x.y + x.z*x.z + x.w*x.w;
          hp[c*2]   = packsplit(x.x, x.y, lp[c*2]);
          hp[c*2+1] = packsplit(x.z, x.w, lp[c*2+1]);
        }
        *(uint4*)(smc + KHI + o0) = make_uint4(hp[0], hp[1], hp[2], hp[3]);
        *(uint4*)(smc + KHI + o1) = make_uint4(hp[4], hp[5], hp[6], hp[7]);
        *(uint4*)(smc + KLO + o0) = make_uint4(lp[0], lp[1], lp[2], lp[3]);
        *(uint4*)(smc + KLO + o1) = make_uint4(lp[4], lp[5], lp[6], lp[7]);
      }
      ((float*)(smc + K2P))[r*4 + c4] = k2p;
      {
        u32 hp[8], lp[8];
        #pragma unroll
        for (int c = 0; c < 4; c++){
          float4 x = *(const float4*)(vsrc + c*4);
          hp[c*2]   = packsplit(x.x, x.y, lp[c*2]);
          hp[c*2+1] = packsplit(x.z, x.w, lp[c*2+1]);
        }
        *(uint4*)(smc + VHI + o0) = make_uint4(hp[0], hp[1], hp[2], hp[3]);
        *(uint4*)(smc + VHI + o1) = make_uint4(hp[4], hp[5], hp[6], hp[7]);
        *(uint4*)(smc + VLO + o0) = make_uint4(lp[0], lp[1], lp[2], lp[3]);
        *(uint4*)(smc + VLO + o1) = make_uint4(lp[4], lp[5], lp[6], lp[7]);
      }
    }
    __syncthreads();

    // finalize k2 while everyone starts S mmas (k2s consumed after next barrier)
    if (tid < BN){
      const float* kp = (const float*)(smc + K2P) + tid*4;
      ((float*)(smc + K2S))[tid] = (kp[0] + kp[1]) + (kp[2] + kp[3]);
    }

    // ---- S = Q @ K^T, 3-term fp16 split; K fragments via ldmatrix.x4 ----
    float sacc[NTILES][4];
    #pragma unroll
    for (int t = 0; t < NTILES; t++){
      sacc[t][0]=0.f; sacc[t][1]=0.f; sacc[t][2]=0.f; sacc[t][3]=0.f;
    }
    #pragma unroll
    for (int nt = 0; nt < NTILES; nt++){
      #pragma unroll
      for (int ks2 = 0; ks2 < 2; ks2++){
        const u32 off = swz(kfrag + (u32)(nt*1024 + ks2*64));
        u32 h0,h1,h2,h3, l0,l1,l2,l3;
        ldm4(smb + KHI + off, h0, h1, h2, h3);
        ldm4(smb + KLO + off, l0, l1, l2, l3);
        const int ka = 2*ks2, kb = 2*ks2 + 1;
        mma16816(sacc[nt], aqh[ka][0], aqh[ka][1], aqh[ka][2], aqh[ka][3], h0, h1);
        mma16816(sacc[nt], aqh[ka][0], aqh[ka][1], aqh[ka][2], aqh[ka][3], l0, l1);
        mma16816(sacc[nt], aql[ka][0], aql[ka][1], aql[ka][2], aql[ka][3], h0, h1);
        mma16816(sacc[nt], aqh[kb][0], aqh[kb][1], aqh[kb][2], aqh[kb][3], h2, h3);
        mma16816(sacc[nt], aqh[kb][0], aqh[kb][1], aqh[kb][2], aqh[kb][3], l2, l3);
        mma16816(sacc[nt], aql[kb][0], aql[kb][1], aql[kb][2], aql[kb][3], h2, h3);
      }
    }
    __syncthreads();   // k2s visible to all

    // ---- logits + online softmax (per-warp rows, shuffle over 4 lanes) ----
    float mx0 = -1e30f, mx1 = -1e30f;
    #pragma unroll
    for (int nt = 0; nt < NTILES; nt++){
      const float2 kk = *(const float2*)((const float*)(smc + K2S) + nt*8 + qc*2);
      const float2 g0 = *(const float2*)(grow + m0 + nt*8);
      const float2 g1 = *(const float2*)(grow + 8*N_ + m0 + nt*8);
      float t00 = C2*(2.f*sacc[nt][0] - kk.x + g0.x);
      float t01 = C2*(2.f*sacc[nt][1] - kk.y + g0.y);
      float t10 = C2*(2.f*sacc[nt][2] - kk.x + g1.x);
      float t11 = C2*(2.f*sacc[nt][3] - kk.y + g1.y);
      sacc[nt][0]=t00; sacc[nt][1]=t01; sacc[nt][2]=t10; sacc[nt][3]=t11;
      mx0 = fmaxf(mx0, fmaxf(t00, t01));
      mx1 = fmaxf(mx1, fmaxf(t10, t11));
    }
    #pragma unroll
    for (int d = 1; d < 4; d <<= 1){
      mx0 = fmaxf(mx0, __shfl_xor_sync(0xffffffffu, mx0, d));
      mx1 = fmaxf(mx1, __shfl_xor_sync(0xffffffffu, mx1, d));
    }
    const float mnew0 = fmaxf(mold0, mx0), mnew1 = fmaxf(mold1, mx1);
    const float al0 = ex2(mold0 - mnew0), al1 = ex2(mold1 - mnew1);
    mold0 = mnew0; mold1 = mnew1;
    float ps0 = 0.f, ps1 = 0.f;
    #pragma unroll
    for (int nt = 0; nt < NTILES; nt++){
      float p0 = ex2(sacc[nt][0] - mnew0);
      float p1 = ex2(sacc[nt][1] - mnew0);
      float p2 = ex2(sacc[nt][2] - mnew1);
      float p3 = ex2(sacc[nt][3] - mnew1);
      sacc[nt][0]=p0; sacc[nt][1]=p1; sacc[nt][2]=p2; sacc[nt][3]=p3;
      ps0 += p0 + p1; ps1 += p2 + p3;
    }
    #pragma unroll
    for (int d = 1; d < 4; d <<= 1){
      ps0 += __shfl_xor_sync(0xffffffffu, ps0, d);
      ps1 += __shfl_xor_sync(0xffffffffu, ps1, d);
    }
    ls0 = ls0*al0 + ps0;
    ls1 = ls1*al1 + ps1;
    #pragma unroll
    for (int t = 0; t < NTILES; t++){
      oacc[t][0]*=al0; oacc[t][1]*=al0; oacc[t][2]*=al1; oacc[t][3]*=al1;
    }

    // ---- O += P @ V : P single fp16, V hi/lo (2 MMAs); V frags via ldmatrix.trans ----
    #pragma unroll
    for (int ks = 0; ks < 4; ks++){
      const u32 a0 = packh(sacc[2*ks][0],   sacc[2*ks][1]);
      const u32 a1 = packh(sacc[2*ks][2],   sacc[2*ks][3]);
      const u32 a2 = packh(sacc[2*ks+1][0], sacc[2*ks+1][1]);
      const u32 a3 = packh(sacc[2*ks+1][2], sacc[2*ks+1][3]);
      #pragma unroll
      for (int dt2 = 0; dt2 < 4; dt2++){
        const u32 off = swz(vfrag + (u32)(ks*2048 + dt2*32));
        u32 h0,h1,h2,h3, l0,l1,l2,l3;
        ldm4t(smb + VHI + off, h0, h1, h2, h3);
        ldm4t(smb + VLO + off, l0, l1, l2, l3);
        mma16816(oacc[2*dt2],   a0, a1, a2, a3, h0, h1);
        mma16816(oacc[2*dt2],   a0, a1, a2, a3, l0, l1);
        mma16816(oacc[2*dt2+1], a0, a1, a2, a3, h2, h3);
        mma16816(oacc[2*dt2+1], a0, a1, a2, a3, l2, l3);
      }
    }
  }

  // ---- epilogue ----
  {
    const float inv0 = 1.f / ls0, inv1 = 1.f / ls1;
    float* ob = out + ((size_t)(b*N_ + n0 + r0)*H_ + h)*D_ + qc*2;
    #pragma unroll
    for (int dt = 0; dt < NTILES; dt++){
      float2 r4a; r4a.x = oacc[dt][0]*inv0; r4a.y = oacc[dt][1]*inv0;
      float2 r4b; r4b.x = oacc[dt][2]*inv1; r4b.y = oacc[dt][3]*inv1;
      *(float2*)(ob + dt*8) = r4a;
      *(float2*)(ob + 8*rowstride + dt*8) = r4b;
    }
  }
}

extern "C" void kernel_launch(void* const* d_in, const int* in_sizes, int n_in,
                              void* d_out, int out_size) {
  const float* q = (const float*)d_in[0];
  const float* k = (const float*)d_in[1];
  const float* v = (const float*)d_in[2];
  const float* g = (const float*)d_in[3];
  float* out = (float*)d_out;

  cudaFuncSetAttribute(geo_attn_mma, cudaFuncAttributeMaxDynamicSharedMemorySize, SMEM_BYTES);
  dim3 grid(N_/BM, H_, B_);
  geo_attn_mma<<<grid, 256, SMEM_BYTES>>>(q, k, v, g, out);
}

// round 5
// speedup vs baseline: 2.7585x; 1.1666x over previous
#include <cuda_runtime.h>
#include <cuda_fp16.h>

#define B_ 16
#define N_ 512
#define H_ 8
#define D_ 64
#define BM 128
#define BN 64
#define NTILES 8
// C2 = 8*log2(e): base-2 logit scale (sqrt(D)=8 folded); C4 = 2*C2 pre-applied to Q
#define C2 11.541560327111707f
#define C4 23.083120654223414f

// per-stage smem byte offsets (stage = K hi/lo + V hi + k2c)
#define KHI 0
#define KLO 8192
#define VHI 16384
#define K2C 24576
#define STG 24832
#define SMEM_BYTES (2*STG)

typedef unsigned int u32;

__device__ __forceinline__ u32 swz(u32 x){ return x ^ ((x >> 3) & 0x70u); }

__device__ __forceinline__ u32 s2u(const void* p){
  u32 a; asm("{ .reg .u64 t; cvta.to.shared.u64 t, %1; cvt.u32.u64 %0, t; }" : "=r"(a) : "l"(p));
  return a;
}
__device__ __forceinline__ float ex2(float x){
  float r; asm("ex2.approx.f32 %0, %1;" : "=f"(r) : "f"(x)); return r;
}
__device__ __forceinline__ u32 packsplit(float a, float b, u32& lo){
  __half ha = __float2half_rn(a), hb = __float2half_rn(b);
  __half la = __float2half_rn(a - __half2float(ha));
  __half lb = __float2half_rn(b - __half2float(hb));
  lo = (u32)__half_as_ushort(la) | ((u32)__half_as_ushort(lb) << 16);
  return (u32)__half_as_ushort(ha) | ((u32)__half_as_ushort(hb) << 16);
}
__device__ __forceinline__ u32 packh(float a, float b){
  __half ha = __float2half_rn(a), hb = __float2half_rn(b);
  return (u32)__half_as_ushort(ha) | ((u32)__half_as_ushort(hb) << 16);
}
__device__ __forceinline__ void mma16816(float* c, u32 a0, u32 a1, u32 a2, u32 a3,
                                         u32 b0, u32 b1){
  asm volatile(
    "mma.sync.aligned.m16n8k16.row.col.f32.f16.f16.f32 "
    "{%0,%1,%2,%3}, {%4,%5,%6,%7}, {%8,%9}, {%0,%1,%2,%3};"
    : "+f"(c[0]), "+f"(c[1]), "+f"(c[2]), "+f"(c[3])
    : "r"(a0), "r"(a1), "r"(a2), "r"(a3), "r"(b0), "r"(b1));
}
__device__ __forceinline__ void ldm4(u32 addr, u32& r0, u32& r1, u32& r2, u32& r3){
  asm volatile("ldmatrix.sync.aligned.m8n8.x4.shared.b16 {%0,%1,%2,%3}, [%4];"
    : "=r"(r0), "=r"(r1), "=r"(r2), "=r"(r3) : "r"(addr));
}
__device__ __forceinline__ void ldm4t(u32 addr, u32& r0, u32& r1, u32& r2, u32& r3){
  asm volatile("ldmatrix.sync.aligned.m8n8.x4.trans.shared.b16 {%0,%1,%2,%3}, [%4];"
    : "=r"(r0), "=r"(r1), "=r"(r2), "=r"(r3) : "r"(addr));
}

// LDG + fp16 convert + STS for one 64-key tile into stage 'st' (byte offset)
__device__ __forceinline__ void load_tile(char* smc, u32 st,
    const float* __restrict__ ksrc0, const float* __restrict__ vsrc0, int tid){
  const int r = tid >> 2, c4 = tid & 3, d0 = c4 * 16;
  const float* ksrc = ksrc0 + (size_t)r*(H_*D_) + d0;
  const float* vsrc = vsrc0 + (size_t)r*(H_*D_) + d0;
  const u32 o0 = swz((u32)(r*128 + d0*2));
  const u32 o1 = swz((u32)(r*128 + d0*2 + 16));
  float k2p = 0.f;
  {
    u32 hp[8], lp[8];
    #pragma unroll
    for (int c = 0; c < 4; c++){
      float4 x = *(const float4*)(ksrc + c*4);
      k2p += x.x*x.x + x.y*x.y + x.z*x.z + x.w*x.w;
      hp[c*2]   = packsplit(x.x, x.y, lp[c*2]);
      hp[c*2+1] = packsplit(x.z, x.w, lp[c*2+1]);
    }
    *(uint4*)(smc + st + KHI + o0) = make_uint4(hp[0], hp[1], hp[2], hp[3]);
    *(uint4*)(smc + st + KHI + o1) = make_uint4(hp[4], hp[5], hp[6], hp[7]);
    *(uint4*)(smc + st + KLO + o0) = make_uint4(lp[0], lp[1], lp[2], lp[3]);
    *(uint4*)(smc + st + KLO + o1) = make_uint4(lp[4], lp[5], lp[6], lp[7]);
  }
  // full ||k||^2 for this key row via 2 shuffles (lanes differing in bits 0-1 share a row)
  k2p += __shfl_xor_sync(0xffffffffu, k2p, 1);
  k2p += __shfl_xor_sync(0xffffffffu, k2p, 2);
  if (c4 == 0) ((float*)(smc + st + K2C))[r] = C2 * k2p;
  {
    u32 vp[8];
    #pragma unroll
    for (int c = 0; c < 4; c++){
      float4 x = *(const float4*)(vsrc + c*4);
      vp[c*2]   = packh(x.x, x.y);
      vp[c*2+1] = packh(x.z, x.w);
    }
    *(uint4*)(smc + st + VHI + o0) = make_uint4(vp[0], vp[1], vp[2], vp[3]);
    *(uint4*)(smc + st + VHI + o1) = make_uint4(vp[4], vp[5], vp[6], vp[7]);
  }
}

__global__ void __launch_bounds__(256, 2) geo_attn_mma(
    const float* __restrict__ q, const float* __restrict__ k,
    const float* __restrict__ v, const float* __restrict__ geo,
    float* __restrict__ out)
{
  extern __shared__ __align__(128) char smc[];
  const u32 smb = s2u(smc);
  const int tid = threadIdx.x, w = tid >> 5, l = tid & 31;
  const int qr = l >> 2;
  const int qc = l & 3;
  const int r0 = w * 16 + qr;
  const int qt = blockIdx.x, h = blockIdx.y, b = blockIdx.z;
  const int n0 = qt * BM;
  const int rowstride = H_ * D_;

  const u32 kfrag = (u32)((l & 7) * 128 + (l >> 3) * 16);
  const u32 vfrag = (u32)(((l >> 3) & 1) * 1024 + (l & 7) * 128 + (l >> 4) * 16);

  const float* kb = k + ((size_t)b*N_*H_ + h)*D_;
  const float* vb = v + ((size_t)b*N_*H_ + h)*D_;

  // ---- Q A-fragments from global, pre-scaled by 2*C2, fp16 hi/lo split ----
  u32 aqh[4][4], aql[4][4];
  {
    const float* qb = q + ((size_t)(b*N_ + n0 + r0)*H_ + h)*D_;
    #pragma unroll
    for (int ks = 0; ks < 4; ks++){
      const int c0 = ks*16 + qc*2;
      float2 x00 = *(const float2*)(qb + c0);
      float2 x10 = *(const float2*)(qb + 8*rowstride + c0);
      float2 x01 = *(const float2*)(qb + c0 + 8);
      float2 x11 = *(const float2*)(qb + 8*rowstride + c0 + 8);
      aqh[ks][0] = packsplit(C4*x00.x, C4*x00.y, aql[ks][0]);
      aqh[ks][1] = packsplit(C4*x10.x, C4*x10.y, aql[ks][1]);
      aqh[ks][2] = packsplit(C4*x01.x, C4*x01.y, aql[ks][2]);
      aqh[ks][3] = packsplit(C4*x11.x, C4*x11.y, aql[ks][3]);
    }
  }

  float oacc[NTILES][4];
  #pragma unroll
  for (int t = 0; t < NTILES; t++){
    oacc[t][0]=0.f; oacc[t][1]=0.f; oacc[t][2]=0.f; oacc[t][3]=0.f;
  }
  float mold0 = -1e30f, mold1 = -1e30f, ls0 = 0.f, ls1 = 0.f;

  const float* grow = geo + (size_t)b*(N_*N_) + (size_t)(n0 + r0)*N_ + qc*2;

  // prologue: fill stage 0
  load_tile(smc, 0, kb, vb, tid);
  __syncthreads();

  for (int mt = 0; mt < NTILES; mt++){
    const int m0 = mt * BN;
    const u32 st = (u32)(mt & 1) * STG;

    // prefetch next tile into the other stage (no barrier until end of iter)
    if (mt < NTILES-1){
      const u32 stn = (u32)((mt+1) & 1) * STG;
      load_tile(smc, stn, kb + (size_t)(m0+BN)*rowstride, vb + (size_t)(m0+BN)*rowstride, tid);
    }

    // ---- S = Q @ K^T (3-term fp16 split) ----
    float sacc[NTILES][4];
    #pragma unroll
    for (int t = 0; t < NTILES; t++){
      sacc[t][0]=0.f; sacc[t][1]=0.f; sacc[t][2]=0.f; sacc[t][3]=0.f;
    }
    #pragma unroll
    for (int nt = 0; nt < NTILES; nt++){
      #pragma unroll
      for (int ks2 = 0; ks2 < 2; ks2++){
        const u32 off = swz(kfrag + (u32)(nt*1024 + ks2*64));
        u32 h0,h1,h2,h3, l0,l1,l2,l3;
        ldm4(smb + st + KHI + off, h0, h1, h2, h3);
        ldm4(smb + st + KLO + off, l0, l1, l2, l3);
        const int ka = 2*ks2, kb2 = 2*ks2 + 1;
        mma16816(sacc[nt], aqh[ka][0], aqh[ka][1], aqh[ka][2], aqh[ka][3], h0, h1);
        mma16816(sacc[nt], aqh[ka][0], aqh[ka][1], aqh[ka][2], aqh[ka][3], l0, l1);
        mma16816(sacc[nt], aql[ka][0], aql[ka][1], aql[ka][2], aql[ka][3], h0, h1);
        mma16816(sacc[nt], aqh[kb2][0], aqh[kb2][1], aqh[kb2][2], aqh[kb2][3], h2, h3);
        mma16816(sacc[nt], aqh[kb2][0], aqh[kb2][1], aqh[kb2][2], aqh[kb2][3], l2, l3);
        mma16816(sacc[nt], aql[kb2][0], aql[kb2][1], aql[kb2][2], aql[kb2][3], h2, h3);
      }
    }

    // ---- logits + online softmax ----
    float mx0 = -1e30f, mx1 = -1e30f;
    #pragma unroll
    for (int nt = 0; nt < NTILES; nt++){
      const float2 kk = *(const float2*)((const float*)(smc + st + K2C) + nt*8 + qc*2);
      const float2 g0 = *(const float2*)(grow + m0 + nt*8);
      const float2 g1 = *(const float2*)(grow + 8*N_ + m0 + nt*8);
      float t00 = fmaf(C2, g0.x, sacc[nt][0] - kk.x);
      float t01 = fmaf(C2, g0.y, sacc[nt][1] - kk.y);
      float t10 = fmaf(C2, g1.x, sacc[nt][2] - kk.x);
      float t11 = fmaf(C2, g1.y, sacc[nt][3] - kk.y);
      sacc[nt][0]=t00; sacc[nt][1]=t01; sacc[nt][2]=t10; sacc[nt][3]=t11;
      mx0 = fmaxf(mx0, fmaxf(t00, t01));
      mx1 = fmaxf(mx1, fmaxf(t10, t11));
    }
    #pragma unroll
    for (int d = 1; d < 4; d <<= 1){
      mx0 = fmaxf(mx0, __shfl_xor_sync(0xffffffffu, mx0, d));
      mx1 = fmaxf(mx1, __shfl_xor_sync(0xffffffffu, mx1, d));
    }
    const float mnew0 = fmaxf(mold0, mx0), mnew1 = fmaxf(mold1, mx1);
    const float al0 = ex2(mold0 - mnew0), al1 = ex2(mold1 - mnew1);
    mold0 = mnew0; mold1 = mnew1;
    float ps0 = 0.f, ps1 = 0.f;
    #pragma unroll
    for (int nt = 0; nt < NTILES; nt++){
      float p0 = ex2(sacc[nt][0] - mnew0);
      float p1 = ex2(sacc[nt][1] - mnew0);
      float p2 = ex2(sacc[nt][2] - mnew1);
      float p3 = ex2(sacc[nt][3] - mnew1);
      sacc[nt][0]=p0; sacc[nt][1]=p1; sacc[nt][2]=p2; sacc[nt][3]=p3;
      ps0 += p0 + p1; ps1 += p2 + p3;
    }
    #pragma unroll
    for (int d = 1; d < 4; d <<= 1){
      ps0 += __shfl_xor_sync(0xffffffffu, ps0, d);
      ps1 += __shfl_xor_sync(0xffffffffu, ps1, d);
    }
    ls0 = ls0*al0 + ps0;
    ls1 = ls1*al1 + ps1;
    #pragma unroll
    for (int t = 0; t < NTILES; t++){
      oacc[t][0]*=al0; oacc[t][1]*=al0; oacc[t][2]*=al1; oacc[t][3]*=al1;
    }

    // ---- O += P @ V : P single fp16, V single fp16 ----
    #pragma unroll
    for (int ks = 0; ks < 4; ks++){
      const u32 a0 = packh(sacc[2*ks][0],   sacc[2*ks][1]);
      const u32 a1 = packh(sacc[2*ks][2],   sacc[2*ks][3]);
      const u32 a2 = packh(sacc[2*ks+1][0], sacc[2*ks+1][1]);
      const u32 a3 = packh(sacc[2*ks+1][2], sacc[2*ks+1][3]);
      #pragma unroll
      for (int dt2 = 0; dt2 < 4; dt2++){
        const u32 off = swz(vfrag + (u32)(ks*2048 + dt2*32));
        u32 h0,h1,h2,h3;
        ldm4t(smb + st + VHI + off, h0, h1, h2, h3);
        mma16816(oacc[2*dt2],   a0, a1, a2, a3, h0, h1);
        mma16816(oacc[2*dt2+1], a0, a1, a2, a3, h2, h3);
      }
    }

    __syncthreads();   // stage[mt&1] reads done; next iter may overwrite it
  }

  // ---- epilogue ----
  {
    const float inv0 = 1.f / ls0, inv1 = 1.f / ls1;
    float* ob = out + ((size_t)(b*N_ + n0 + r0)*H_ + h)*D_ + qc*2;
    #pragma unroll
    for (int dt = 0; dt < NTILES; dt++){
      float2 r4a; r4a.x = oacc[dt][0]*inv0; r4a.y = oacc[dt][1]*inv0;
      float2 r4b; r4b.x = oacc[dt][2]*inv1; r4b.y = oacc[dt][3]*inv1;
      *(float2*)(ob + dt*8) = r4a;
      *(float2*)(ob + 8*rowstride + dt*8) = r4b;
    }
  }
}

extern "C" void kernel_launch(void* const* d_in, const int* in_sizes, int n_in,
                              void* d_out, int out_size) {
  const float* q = (const float*)d_in[0];
  const float* k = (const float*)d_in[1];
  const float* v = (const float*)d_in[2];
  const float* g = (const float*)d_in[3];
  float* out = (float*)d_out;

  cudaFuncSetAttribute(geo_attn_mma, cudaFuncAttributeMaxDynamicSharedMemorySize, SMEM_BYTES);
  dim3 grid(N_/BM, H_, B_);
  geo_attn_mma<<<grid, 256, SMEM_BYTES>>>(q, k, v, g, out);
}